// round 2
// baseline (speedup 1.0000x reference)
#include <cuda_runtime.h>
#include <math.h>
#include <stdint.h>

#define NB    4096
#define NN    524288
#define HDIM  128
#define NBLK  (NN / 128)

// ---------------- static device scratch (no allocs) ----------------
__device__ int   g_off[NB + 1];
__device__ float g_frag_m [NB + NBLK];        // fragment local max
__device__ float g_frag_se[NB + NBLK];        // fragment sum of exp
__device__ float g_frag_v [(NB + NBLK) * 128];// fragment weighted feature sum
__device__ float g_x[NB * 256];               // [query | pooled]

__device__ __forceinline__ float fast_tanh(float x) {
    float e = __expf(2.0f * x);
    return 1.0f - __fdividef(2.0f, e + 1.0f);
}

// ===========================================================================
// Kernel 1: scores GEMM + fragment softmax partials (flash-style), fused
//           with segment-offset computation.
// ===========================================================================
#define AS_LD 129
#define SM_W1 (128 * AS_LD)          // A tile: 128x128 pad-129
#define SM_W2 (SM_W1 + 128 * 64)     // W1: 128x64
#define SM_B1 (SM_W2 + 64)
#define SM_TOT (SM_B1 + 64)          // 24832 floats = 99328 bytes dynamic

__global__ __launch_bounds__(128) void scores_kernel(
    const float* __restrict__ ball, const int* __restrict__ batch,
    const float* __restrict__ w1, const float* __restrict__ b1,
    const float* __restrict__ w2, const float* __restrict__ b2)
{
    extern __shared__ float sm[];
    float* As  = sm;
    float* W1s = sm + SM_W1;
    float* w2s = sm + SM_W2;
    float* b1s = sm + SM_B1;

    __shared__ float sc[128], esc[128], red[8 * 128];
    __shared__ float fm[128], fse[128];
    __shared__ int   bbs[128], fid_s[128], lastf[128], fstart[128], fend[128];
    __shared__ int   wcnt[4];

    const int t   = threadIdx.x;
    const int blk = blockIdx.x;
    const int lane = t & 31, warp = t >> 5;

    // ---- load A tile, W1, batch ids ----
    const float* Ablk = ball + (size_t)blk * 128 * HDIM;
#pragma unroll
    for (int it = 0; it < 32; it++) {
        int f4 = t + 128 * it;
        int row = f4 >> 5;
        int c = (f4 & 31) << 2;
        float4 v = ((const float4*)Ablk)[f4];
        float* d = &As[row * AS_LD + c];
        d[0] = v.x; d[1] = v.y; d[2] = v.z; d[3] = v.w;
    }
#pragma unroll
    for (int it = 0; it < 16; it++) {
        int f4 = t + 128 * it;
        ((float4*)W1s)[f4] = ((const float4*)w1)[f4];
    }
    if (t < 64) { w2s[t] = w2[t]; b1s[t] = b1[t]; }
    bbs[t] = batch[blk * 128 + t];
    __syncthreads();

    // ---- segment offsets (g_off), written inline ----
    {
        int myb = bbs[t];
        int pb = (t == 0) ? ((blk == 0) ? -1 : batch[blk * 128 - 1]) : bbs[t - 1];
        for (int s2 = pb + 1; s2 <= myb; s2++) g_off[s2] = blk * 128 + t;
        if (blk == NBLK - 1 && t == 127)
            for (int s2 = myb + 1; s2 <= NB; s2++) g_off[s2] = NN;
    }

    // ---- GEMM: tanh(A @ W1 + b1) @ w2 -> score per row ----
    int tm = t & 15, tn = t >> 4;
    uint64_t acc[8][4];
    {
        const ulonglong2* bi = (const ulonglong2*)&b1s[tn * 8];
        ulonglong2 p0 = bi[0], p1 = bi[1];
#pragma unroll
        for (int r = 0; r < 8; r++) {
            acc[r][0] = p0.x; acc[r][1] = p0.y;
            acc[r][2] = p1.x; acc[r][3] = p1.y;
        }
    }
#pragma unroll 2
    for (int k = 0; k < 128; k++) {
        const ulonglong2* bp = (const ulonglong2*)&W1s[k * 64 + tn * 8];
        ulonglong2 q0 = bp[0], q1 = bp[1];
        uint64_t bb0 = q0.x, bb1 = q0.y, bb2 = q1.x, bb3 = q1.y;
#pragma unroll
        for (int r = 0; r < 8; r++) {
            float a = As[(tm + 16 * r) * AS_LD + k];
            uint64_t a2;
            asm("mov.b64 %0, {%1, %1};" : "=l"(a2) : "f"(a));
            asm("fma.rn.f32x2 %0, %1, %2, %0;" : "+l"(acc[r][0]) : "l"(a2), "l"(bb0));
            asm("fma.rn.f32x2 %0, %1, %2, %0;" : "+l"(acc[r][1]) : "l"(a2), "l"(bb1));
            asm("fma.rn.f32x2 %0, %1, %2, %0;" : "+l"(acc[r][2]) : "l"(a2), "l"(bb2));
            asm("fma.rn.f32x2 %0, %1, %2, %0;" : "+l"(acc[r][3]) : "l"(a2), "l"(bb3));
        }
    }
    float w2v[8];
#pragma unroll
    for (int c = 0; c < 8; c++) w2v[c] = w2s[tn * 8 + c];
#pragma unroll
    for (int r = 0; r < 8; r++) {
        float p = 0.f;
#pragma unroll
        for (int i = 0; i < 4; i++) {
            float lo, hi;
            asm("mov.b64 {%0, %1}, %2;" : "=f"(lo), "=f"(hi) : "l"(acc[r][i]));
            p += fast_tanh(lo) * w2v[2 * i] + fast_tanh(hi) * w2v[2 * i + 1];
        }
        red[tn * 128 + tm + 16 * r] = p;
    }
    __syncthreads();
    {
        float s = b2[0];
#pragma unroll
        for (int q = 0; q < 8; q++) s += red[q * 128 + t];
        sc[t] = s;
    }

    // ---- fragment ids (segmented positions within tile) ----
    int newf = (t == 0) ? 1 : (bbs[t] != bbs[t - 1]);
    unsigned bal = __ballot_sync(0xffffffffu, newf);
    if (lane == 0) wcnt[warp] = __popc(bal);
    int last = (t == 127) ? 1 : (bbs[t + 1] != bbs[t]);
    lastf[t] = last;
    __syncthreads();
    int base = 0;
    for (int wq = 0; wq < warp; wq++) base += wcnt[wq];
    int fid = base + __popc(bal & ((2u << lane) - 1u)) - 1;
    fid_s[t] = fid;
    if (newf) fstart[fid] = t;
    if (last) fend[fid]   = t + 1;
    __syncthreads();

    int nf = fid_s[127] + 1;

    // ---- per-fragment max & sumexp (serial per fragment -> deterministic) ----
    if (t < nf) {
        int fs = fstart[t], fe = fend[t];
        float m = -3.4e38f;
        for (int i = fs; i < fe; i++) m = fmaxf(m, sc[i]);
        float se = 0.f;
        for (int i = fs; i < fe; i++) se += __expf(sc[i] - m);
        fm[t] = m; fse[t] = se;
        int id = bbs[fs] + blk;
        g_frag_m[id]  = m;
        g_frag_se[id] = se;
    }
    __syncthreads();
    esc[t] = __expf(sc[t] - fm[fid_s[t]]);
    __syncthreads();

    // ---- fragment weighted feature sums: thread t = column t ----
    {
        float a = 0.f;
#pragma unroll 4
        for (int i = 0; i < 128; i++) {
            a += esc[i] * As[i * AS_LD + t];
            if (lastf[i]) {
                g_frag_v[(size_t)(bbs[i] + blk) * 128 + t] = a;
                a = 0.f;
            }
        }
    }
}

// ===========================================================================
// Kernel 2: combine fragments per segment -> x = [query | pooled]  (B x 256)
// ===========================================================================
__global__ __launch_bounds__(128) void reduce_kernel(
    const float* __restrict__ query)
{
    int s = blockIdx.x;
    int t = threadIdx.x;
    int o0 = g_off[s], o1 = g_off[s + 1];
    float pooled = 0.f;
    if (o0 < o1) {
        int kb0 = o0 >> 7, kb1 = (o1 - 1) >> 7;
        float M = -3.4e38f;
        for (int k = kb0; k <= kb1; k++) M = fmaxf(M, g_frag_m[s + k]);
        float denom = 0.f;
        for (int k = kb0; k <= kb1; k++)
            denom += g_frag_se[s + k] * __expf(g_frag_m[s + k] - M);
        float inv = 1.0f / denom;
        for (int k = kb0; k <= kb1; k++)
            pooled += g_frag_v[(size_t)(s + k) * 128 + t] * __expf(g_frag_m[s + k] - M);
        pooled *= inv;
    }
    g_x[s * 256 + t]       = query[(size_t)s * 128 + t];
    g_x[s * 256 + 128 + t] = pooled;
}

// ===========================================================================
// Kernel 3: batched combiner GEMM + LN + GELU + both heads.
// 128 blocks x 256 threads, 32 segment-rows per block. Weights in SMEM.
// ===========================================================================
#define XLD 260
#define MS_XS 0                         // xs: 32 x 260
#define MS_WS (32 * XLD)                // ws: 64 x 128 (k-chunk)  (hw overlays xs+ws)
#define MS_HS (MS_WS + 64 * 128)        // hs: 32 x 132
#define MS_CB (MS_HS + 32 * 132)        // comb_b 128
#define MS_LG (MS_CB + 128)
#define MS_LB (MS_LG + 128)
#define MS_W2 (MS_LB + 128)             // [bnd_w2 | wkt_w2] 128
#define MS_B1 (MS_W2 + 128)             // [bnd_b1 | wkt_b1] 128
#define MS_TOT (MS_B1 + 128)            // 21376 floats = 85504 B

__global__ __launch_bounds__(256) void mlp_kernel(
    const float* __restrict__ comb_w, const float* __restrict__ comb_b,
    const float* __restrict__ ln_g, const float* __restrict__ ln_b,
    const float* __restrict__ bnd_w1, const float* __restrict__ bnd_b1,
    const float* __restrict__ bnd_w2, const float* __restrict__ bnd_b2,
    const float* __restrict__ wkt_w1, const float* __restrict__ wkt_b1,
    const float* __restrict__ wkt_w2, const float* __restrict__ wkt_b2,
    float* __restrict__ out)
{
    extern __shared__ float ms[];
    float* xs = ms + MS_XS;
    float* ws = ms + MS_WS;
    float* hw = ms;                    // overlays xs+ws in head phase
    float* hs = ms + MS_HS;
    float* cb = ms + MS_CB;
    float* lg = ms + MS_LG;
    float* lb = ms + MS_LB;
    float* w2s = ms + MS_W2;
    float* b1s = ms + MS_B1;

    const int t = threadIdx.x;
    const int blk = blockIdx.x;
    const int r = t >> 3;              // 0..31 row
    const int cg = t & 7;              // 0..7 col group
    const int c0 = cg * 16;

    // load x tile (32 rows x 256)
    {
        const float4* src = (const float4*)(g_x + (size_t)blk * 32 * 256);
#pragma unroll
        for (int i = 0; i < 8; i++) {
            int f4 = t + 256 * i;
            int row = f4 >> 6, rem = f4 & 63;
            *(float4*)&xs[row * XLD + rem * 4] = src[f4];
        }
    }
    if (t < 128) {
        cb[t] = comb_b[t]; lg[t] = ln_g[t]; lb[t] = ln_b[t];
        w2s[t] = (t < 64) ? bnd_w2[t] : wkt_w2[t - 64];
        b1s[t] = (t < 64) ? bnd_b1[t] : wkt_b1[t - 64];
    }
    __syncthreads();

    // combiner GEMM: h[32][128] += x[32][256] @ comb_w[256][128]
    uint64_t acc[8];
    {
        const ulonglong2* ci = (const ulonglong2*)&cb[c0];
        ulonglong2 p0 = ci[0], p1 = ci[1], p2 = ci[2], p3 = ci[3];
        acc[0] = p0.x; acc[1] = p0.y; acc[2] = p1.x; acc[3] = p1.y;
        acc[4] = p2.x; acc[5] = p2.y; acc[6] = p3.x; acc[7] = p3.y;
    }
    for (int kt = 0; kt < 256; kt += 64) {
        const float4* src = (const float4*)(comb_w + kt * 128);
#pragma unroll
        for (int i = 0; i < 8; i++) {
            int f4 = t + 256 * i;
            ((float4*)ws)[f4] = src[f4];
        }
        __syncthreads();
#pragma unroll 4
        for (int kk = 0; kk < 64; kk++) {
            float a = xs[r * XLD + kt + kk];
            uint64_t a2;
            asm("mov.b64 %0, {%1, %1};" : "=l"(a2) : "f"(a));
            const ulonglong2* bp = (const ulonglong2*)&ws[kk * 128 + c0];
            ulonglong2 q0 = bp[0], q1 = bp[1], q2 = bp[2], q3 = bp[3];
            asm("fma.rn.f32x2 %0, %1, %2, %0;" : "+l"(acc[0]) : "l"(a2), "l"(q0.x));
            asm("fma.rn.f32x2 %0, %1, %2, %0;" : "+l"(acc[1]) : "l"(a2), "l"(q0.y));
            asm("fma.rn.f32x2 %0, %1, %2, %0;" : "+l"(acc[2]) : "l"(a2), "l"(q1.x));
            asm("fma.rn.f32x2 %0, %1, %2, %0;" : "+l"(acc[3]) : "l"(a2), "l"(q1.y));
            asm("fma.rn.f32x2 %0, %1, %2, %0;" : "+l"(acc[4]) : "l"(a2), "l"(q2.x));
            asm("fma.rn.f32x2 %0, %1, %2, %0;" : "+l"(acc[5]) : "l"(a2), "l"(q2.y));
            asm("fma.rn.f32x2 %0, %1, %2, %0;" : "+l"(acc[6]) : "l"(a2), "l"(q3.x));
            asm("fma.rn.f32x2 %0, %1, %2, %0;" : "+l"(acc[7]) : "l"(a2), "l"(q3.y));
        }
        __syncthreads();
    }

    // unpack h, LayerNorm over 128 cols (8 threads per row) + GELU
    float h[16];
#pragma unroll
    for (int i = 0; i < 8; i++)
        asm("mov.b64 {%0, %1}, %2;" : "=f"(h[2 * i]), "=f"(h[2 * i + 1]) : "l"(acc[i]));
    float s1 = 0.f;
#pragma unroll
    for (int i = 0; i < 16; i++) s1 += h[i];
    s1 += __shfl_xor_sync(0xffffffffu, s1, 1);
    s1 += __shfl_xor_sync(0xffffffffu, s1, 2);
    s1 += __shfl_xor_sync(0xffffffffu, s1, 4);
    float mu = s1 * (1.0f / 128.0f);
    float s2 = 0.f;
#pragma unroll
    for (int i = 0; i < 16; i++) { float d = h[i] - mu; s2 += d * d; }
    s2 += __shfl_xor_sync(0xffffffffu, s2, 1);
    s2 += __shfl_xor_sync(0xffffffffu, s2, 2);
    s2 += __shfl_xor_sync(0xffffffffu, s2, 4);
    float rstd = rsqrtf(s2 * (1.0f / 128.0f) + 1e-5f);
#pragma unroll
    for (int i = 0; i < 16; i++) {
        float v = (h[i] - mu) * rstd * lg[c0 + i] + lb[c0 + i];
        v = 0.5f * v * (1.0f + erff(v * 0.70710678118654752f));
        hs[r * 132 + c0 + i] = v;
    }
    __syncthreads();

    // load head weights, overlaying xs/ws
    {
        const float4* sb = (const float4*)bnd_w1;
        const float4* sw = (const float4*)wkt_w1;
#pragma unroll
        for (int i = 0; i < 8; i++) {
            int f4 = t + 256 * i;               // 2048 float4 each
            int k = f4 >> 4, j0 = (f4 & 15) * 4;
            *(float4*)&hw[k * 128 + j0]      = sb[f4];
            *(float4*)&hw[k * 128 + 64 + j0] = sw[f4];
        }
    }
    __syncthreads();

    // heads: thread computes 16 hidden units j = c0..c0+15 (cg<4 -> bnd, cg>=4 -> wkt)
    uint64_t ah[8];
    {
        const ulonglong2* bi = (const ulonglong2*)&b1s[c0];
        ulonglong2 p0 = bi[0], p1 = bi[1], p2 = bi[2], p3 = bi[3];
        ah[0] = p0.x; ah[1] = p0.y; ah[2] = p1.x; ah[3] = p1.y;
        ah[4] = p2.x; ah[5] = p2.y; ah[6] = p3.x; ah[7] = p3.y;
    }
#pragma unroll 4
    for (int k = 0; k < 128; k++) {
        float a = hs[r * 132 + k];
        uint64_t a2;
        asm("mov.b64 %0, {%1, %1};" : "=l"(a2) : "f"(a));
        const ulonglong2* bp = (const ulonglong2*)&hw[k * 128 + c0];
        ulonglong2 q0 = bp[0], q1 = bp[1], q2 = bp[2], q3 = bp[3];
        asm("fma.rn.f32x2 %0, %1, %2, %0;" : "+l"(ah[0]) : "l"(a2), "l"(q0.x));
        asm("fma.rn.f32x2 %0, %1, %2, %0;" : "+l"(ah[1]) : "l"(a2), "l"(q0.y));
        asm("fma.rn.f32x2 %0, %1, %2, %0;" : "+l"(ah[2]) : "l"(a2), "l"(q1.x));
        asm("fma.rn.f32x2 %0, %1, %2, %0;" : "+l"(ah[3]) : "l"(a2), "l"(q1.y));
        asm("fma.rn.f32x2 %0, %1, %2, %0;" : "+l"(ah[4]) : "l"(a2), "l"(q2.x));
        asm("fma.rn.f32x2 %0, %1, %2, %0;" : "+l"(ah[5]) : "l"(a2), "l"(q2.y));
        asm("fma.rn.f32x2 %0, %1, %2, %0;" : "+l"(ah[6]) : "l"(a2), "l"(q3.x));
        asm("fma.rn.f32x2 %0, %1, %2, %0;" : "+l"(ah[7]) : "l"(a2), "l"(q3.y));
    }
    float p = 0.f;
#pragma unroll
    for (int i = 0; i < 8; i++) {
        float lo, hi;
        asm("mov.b64 {%0, %1}, %2;" : "=f"(lo), "=f"(hi) : "l"(ah[i]));
        p += fmaxf(lo, 0.f) * w2s[c0 + 2 * i] + fmaxf(hi, 0.f) * w2s[c0 + 2 * i + 1];
    }
    p += __shfl_xor_sync(0xffffffffu, p, 1);
    p += __shfl_xor_sync(0xffffffffu, p, 2);
    int s = blk * 32 + r;
    if (cg == 0) out[s]      = p + bnd_b2[0];
    if (cg == 4) out[NB + s] = p + wkt_b2[0];
}

// ---------------------------------------------------------------------------
extern "C" void kernel_launch(void* const* d_in, const int* in_sizes, int n_in,
                              void* d_out, int out_size) {
    const float* query = (const float*)d_in[0];
    const float* ball  = (const float*)d_in[1];
    const int*   batch = (const int*)d_in[2];
    const float* aw1 = (const float*)d_in[3];
    const float* ab1 = (const float*)d_in[4];
    const float* aw2 = (const float*)d_in[5];
    const float* ab2 = (const float*)d_in[6];
    const float* cw  = (const float*)d_in[7];
    const float* cb  = (const float*)d_in[8];
    const float* lg  = (const float*)d_in[9];
    const float* lb  = (const float*)d_in[10];
    const float* bw1 = (const float*)d_in[11];
    const float* bb1 = (const float*)d_in[12];
    const float* bw2 = (const float*)d_in[13];
    const float* bb2 = (const float*)d_in[14];
    const float* ww1 = (const float*)d_in[15];
    const float* wb1 = (const float*)d_in[16];
    const float* ww2 = (const float*)d_in[17];
    const float* wb2 = (const float*)d_in[18];
    float* out = (float*)d_out;

    constexpr int sc_smem  = SM_TOT * (int)sizeof(float);   // 99328
    constexpr int mlp_smem = MS_TOT * (int)sizeof(float);   // 85504
    cudaFuncSetAttribute(scores_kernel,
                         cudaFuncAttributeMaxDynamicSharedMemorySize, sc_smem);
    cudaFuncSetAttribute(mlp_kernel,
                         cudaFuncAttributeMaxDynamicSharedMemorySize, mlp_smem);

    scores_kernel<<<NBLK, 128, sc_smem>>>(ball, batch, aw1, ab1, aw2, ab2);
    reduce_kernel<<<NB, 128>>>(query);
    mlp_kernel<<<NB / 32, 256, mlp_smem>>>(cw, cb, lg, lb,
                                           bw1, bb1, bw2, bb2,
                                           ww1, wb1, ww2, wb2, out);
}

// round 4
// speedup vs baseline: 1.0853x; 1.0853x over previous
#include <cuda_runtime.h>
#include <math.h>
#include <stdint.h>

#define NB    4096
#define NN    524288
#define HDIM  128
#define NBLK  (NN / 128)

// ---------------- static device scratch ----------------
__device__ int   g_off[NB + 1];
__device__ float g_frag_m [NB + NBLK];
__device__ float g_frag_se[NB + NBLK];
__device__ float g_frag_v [(size_t)(NB + NBLK) * 128];

// ---------------- helpers ----------------
__device__ __forceinline__ float fast_tanh(float x) {
    float e = __expf(2.0f * x);
    return 1.0f - __fdividef(2.0f, e + 1.0f);
}
__device__ __forceinline__ void f32_split(float x, uint32_t& hi, uint32_t& lo) {
    asm("cvt.rna.tf32.f32 %0, %1;" : "=r"(hi) : "f"(x));
    float d = x - __uint_as_float(hi);
    asm("cvt.rna.tf32.f32 %0, %1;" : "=r"(lo) : "f"(d));
}
__device__ __forceinline__ void mma_tf32(float c[4], const uint32_t a[4],
                                         uint32_t b0, uint32_t b1) {
    asm volatile("mma.sync.aligned.m16n8k8.row.col.f32.tf32.tf32.f32 "
        "{%0,%1,%2,%3}, {%4,%5,%6,%7}, {%8,%9}, {%0,%1,%2,%3};"
        : "+f"(c[0]), "+f"(c[1]), "+f"(c[2]), "+f"(c[3])
        : "r"(a[0]), "r"(a[1]), "r"(a[2]), "r"(a[3]), "r"(b0), "r"(b1));
}

#define ALD 132
#define SC_SMEM ((128 * ALD + 64 * ALD) * 4)   // A tile + W1^T = 101376 B

// ===========================================================================
// Kernel 1: 3xTF32 mma.sync scores GEMM + fused fragment-softmax partials
// 512 threads; warp w: m-strip (w>>1)*16, n-half (w&1)*32.
// ===========================================================================
__global__ __launch_bounds__(512, 2) void scores_mma(
    const float* __restrict__ ball, const int* __restrict__ batch,
    const float* __restrict__ w1, const float* __restrict__ b1,
    const float* __restrict__ w2, const float* __restrict__ b2)
{
    extern __shared__ float sm[];
    float* As = sm;               // 128 x 132
    float* WT = sm + 128 * ALD;   // 64 x 132  (W1^T: [n][k])

    __shared__ float sc[128], esc[128], fm[128];
    __shared__ float w2s[64], b1s[64];
    __shared__ float scpart[2][128];
    __shared__ float pv[4][128];
    __shared__ int   bbs[128], fid_s[128], fstart[128], fend[128], wcnt[4];

    const int t = threadIdx.x, blk = blockIdx.x;
    const int wid = t >> 5, lane = t & 31;

    // ---- load A tile (128x128, row-major pad-132) ----
    {
        const float4* Ag = (const float4*)(ball + (size_t)blk * 128 * HDIM);
#pragma unroll
        for (int it = 0; it < 8; it++) {
            int f4 = t + 512 * it;
            int row = f4 >> 5, c = (f4 & 31) * 4;
            *(float4*)&As[row * ALD + c] = Ag[f4];
        }
    }
    // ---- load W1^T (transpose of w1[k=128][n=64]) ----
    {
#pragma unroll
        for (int it = 0; it < 16; it++) {
            int idx = t + 512 * it;
            int k = idx >> 6, n = idx & 63;
            WT[n * ALD + k] = w1[idx];
        }
    }
    if (t < 64) { w2s[t] = w2[t]; b1s[t] = b1[t]; }
    if (t >= 64 && t < 192) bbs[t - 64] = batch[blk * 128 + (t - 64)];
    __syncthreads();

    // ---- segment offsets (inline) ----
    if (t < 128) {
        int myb = bbs[t];
        int pb = (t == 0) ? ((blk == 0) ? -1 : batch[blk * 128 - 1]) : bbs[t - 1];
        for (int s2 = pb + 1; s2 <= myb; s2++) g_off[s2] = blk * 128 + t;
        if (blk == NBLK - 1 && t == 127)
            for (int s2 = myb + 1; s2 <= NB; s2++) g_off[s2] = NN;
    }

    // ---- GEMM: C[m16][n32] per warp via 3xTF32 ----
    const int mrow0 = (wid >> 1) * 16;
    const int ncol0 = (wid & 1) * 32;
    const int lr = lane >> 2, lc = lane & 3;

    float c[4][4];
#pragma unroll
    for (int j = 0; j < 4; j++)
#pragma unroll
        for (int i = 0; i < 4; i++) c[j][i] = 0.f;

#pragma unroll 4
    for (int kt = 0; kt < 16; kt++) {
        int k0 = kt * 8;
        uint32_t ahi[4], alo[4];
        {
            const float* ap = &As[(mrow0 + lr) * ALD + k0 + lc];
            f32_split(ap[0],            ahi[0], alo[0]);
            f32_split(ap[8 * ALD],      ahi[1], alo[1]);
            f32_split(ap[4],            ahi[2], alo[2]);
            f32_split(ap[8 * ALD + 4],  ahi[3], alo[3]);
        }
#pragma unroll
        for (int j = 0; j < 4; j++) {
            const float* bp = &WT[(ncol0 + j * 8 + lr) * ALD + k0 + lc];
            uint32_t bh0, bl0, bh1, bl1;
            f32_split(bp[0], bh0, bl0);
            f32_split(bp[4], bh1, bl1);
            mma_tf32(c[j], ahi, bh0, bh1);
            mma_tf32(c[j], alo, bh0, bh1);
            uint32_t z = 0;
            (void)z;
            mma_tf32(c[j], ahi, bl0, bl1);
        }
    }

    // ---- epilogue: tanh(h + b1) . w2 -> per-row partials ----
    {
        float p0 = 0.f, p1 = 0.f;
#pragma unroll
        for (int j = 0; j < 4; j++) {
            int col0 = ncol0 + j * 8 + 2 * lc;
            float wa = w2s[col0], wb = w2s[col0 + 1];
            float ba = b1s[col0], bb = b1s[col0 + 1];
            p0 += fast_tanh(c[j][0] + ba) * wa + fast_tanh(c[j][1] + bb) * wb;
            p1 += fast_tanh(c[j][2] + ba) * wa + fast_tanh(c[j][3] + bb) * wb;
        }
        p0 += __shfl_xor_sync(0xffffffffu, p0, 1);
        p0 += __shfl_xor_sync(0xffffffffu, p0, 2);
        p1 += __shfl_xor_sync(0xffffffffu, p1, 1);
        p1 += __shfl_xor_sync(0xffffffffu, p1, 2);
        if (lc == 0) {
            scpart[wid & 1][mrow0 + lr]     = p0;
            scpart[wid & 1][mrow0 + lr + 8] = p1;
        }
    }
    __syncthreads();
    if (t < 128) sc[t] = scpart[0][t] + scpart[1][t] + b2[0];
    __syncthreads();

    // ---- fragment ids ----
    int newf = 0, last = 0, fid = 0;
    unsigned bal = 0;
    if (t < 128) {
        newf = (t == 0) ? 1 : (bbs[t] != bbs[t - 1]);
        bal = __ballot_sync(0xffffffffu, newf);
        if (lane == 0) wcnt[wid] = __popc(bal);
        last = (t == 127) ? 1 : (bbs[t + 1] != bbs[t]);
    }
    __syncthreads();
    if (t < 128) {
        int base = 0;
        for (int wq = 0; wq < wid; wq++) base += wcnt[wq];
        fid = base + __popc(bal & ((2u << lane) - 1u)) - 1;
        fid_s[t] = fid;
        if (newf) fstart[fid] = t;
        if (last) fend[fid] = t + 1;
    }
    __syncthreads();
    const int nf = fid_s[127] + 1;

    // ---- per-fragment max & sumexp ----
    if (t < nf) {
        int fs = fstart[t], fe = fend[t];
        float m = -3.4e38f;
        for (int i = fs; i < fe; i++) m = fmaxf(m, sc[i]);
        float se = 0.f;
        for (int i = fs; i < fe; i++) se += __expf(sc[i] - m);
        fm[t] = m;
        int id = bbs[fs] + blk;
        g_frag_m[id]  = m;
        g_frag_se[id] = se;
    }
    __syncthreads();
    if (t < 128) esc[t] = __expf(sc[t] - fm[fid_s[t]]);
    __syncthreads();

    // ---- fragment weighted feature sums (4 threads per column) ----
    {
        int col = t & 127, q = t >> 7;
        for (int f = 0; f < nf; f++) {
            int fs = fstart[f], fe = fend[f];
            float a = 0.f;
            for (int i = fs + q; i < fe; i += 4)
                a += esc[i] * As[i * ALD + col];
            pv[q][col] = a;
            __syncthreads();
            if (q == 0) {
                int id = bbs[fs] + blk;
                g_frag_v[(size_t)id * 128 + col] =
                    (pv[0][col] + pv[1][col]) + (pv[2][col] + pv[3][col]);
            }
            __syncthreads();
        }
    }
}

// ===========================================================================
// Kernel 2: fragment reduce + combiner GEMM + LN + GELU + both heads.
// 128 blocks x 256 threads, 32 segments per block.
// ===========================================================================
#define XLD 260
#define MS_XS 0
#define MS_WS (32 * XLD)
#define MS_HS (MS_WS + 64 * 128)
#define MS_CB (MS_HS + 32 * 132)
#define MS_LG (MS_CB + 128)
#define MS_LB (MS_LG + 128)
#define MS_W2 (MS_LB + 128)
#define MS_B1 (MS_W2 + 128)
#define MS_TOT (MS_B1 + 128)

__global__ __launch_bounds__(256) void mlp_kernel(
    const float* __restrict__ query,
    const float* __restrict__ comb_w, const float* __restrict__ comb_b,
    const float* __restrict__ ln_g, const float* __restrict__ ln_b,
    const float* __restrict__ bnd_w1, const float* __restrict__ bnd_b1,
    const float* __restrict__ bnd_w2, const float* __restrict__ bnd_b2,
    const float* __restrict__ wkt_w1, const float* __restrict__ wkt_b1,
    const float* __restrict__ wkt_w2, const float* __restrict__ wkt_b2,
    float* __restrict__ out)
{
    extern __shared__ float ms[];
    float* xs = ms + MS_XS;
    float* ws = ms + MS_WS;
    float* hw = ms;
    float* hs = ms + MS_HS;
    float* cb = ms + MS_CB;
    float* lg = ms + MS_LG;
    float* lb = ms + MS_LB;
    float* w2s = ms + MS_W2;
    float* b1s = ms + MS_B1;

    const int t = threadIdx.x;
    const int blk = blockIdx.x;
    const int r = t >> 3;
    const int cg = t & 7;
    const int c0 = cg * 16;

    // ---- phase 0: fragment reduce -> xs = [query | pooled] ----
    {
        int s = blk * 32 + r;
        float pooled[16];
#pragma unroll
        for (int j = 0; j < 16; j++) pooled[j] = 0.f;
        int o0 = g_off[s], o1 = g_off[s + 1];
        if (o0 < o1) {
            int kb0 = o0 >> 7, kb1 = (o1 - 1) >> 7;
            float M = -3.4e38f;
            for (int k = kb0; k <= kb1; k++) M = fmaxf(M, g_frag_m[s + k]);
            float denom = 0.f;
            for (int k = kb0; k <= kb1; k++)
                denom += g_frag_se[s + k] * __expf(g_frag_m[s + k] - M);
            float inv = 1.0f / denom;
            for (int k = kb0; k <= kb1; k++) {
                float wg = __expf(g_frag_m[s + k] - M) * inv;
                const float* v = g_frag_v + (size_t)(s + k) * 128 + c0;
#pragma unroll
                for (int j = 0; j < 16; j++) pooled[j] += v[j] * wg;
            }
        }
        const float* q = query + (size_t)s * 128 + c0;
#pragma unroll
        for (int j = 0; j < 16; j++) xs[r * XLD + c0 + j] = q[j];
#pragma unroll
        for (int j = 0; j < 16; j++) xs[r * XLD + 128 + c0 + j] = pooled[j];
    }
    if (t < 128) {
        cb[t] = comb_b[t]; lg[t] = ln_g[t]; lb[t] = ln_b[t];
        w2s[t] = (t < 64) ? bnd_w2[t] : wkt_w2[t - 64];
        b1s[t] = (t < 64) ? bnd_b1[t] : wkt_b1[t - 64];
    }
    __syncthreads();

    // ---- combiner GEMM: h[32][128] = x[32][256] @ comb_w + cb ----
    uint64_t acc[8];
    {
        const ulonglong2* ci = (const ulonglong2*)&cb[c0];
        ulonglong2 p0 = ci[0], p1 = ci[1], p2 = ci[2], p3 = ci[3];
        acc[0] = p0.x; acc[1] = p0.y; acc[2] = p1.x; acc[3] = p1.y;
        acc[4] = p2.x; acc[5] = p2.y; acc[6] = p3.x; acc[7] = p3.y;
    }
    for (int kt = 0; kt < 256; kt += 64) {
        const float4* src = (const float4*)(comb_w + kt * 128);
#pragma unroll
        for (int i = 0; i < 8; i++) {
            int f4 = t + 256 * i;
            ((float4*)ws)[f4] = src[f4];
        }
        __syncthreads();
#pragma unroll 4
        for (int kk = 0; kk < 64; kk++) {
            float a = xs[r * XLD + kt + kk];
            uint64_t a2;
            asm("mov.b64 %0, {%1, %1};" : "=l"(a2) : "f"(a));
            const ulonglong2* bp = (const ulonglong2*)&ws[kk * 128 + c0];
            ulonglong2 q0 = bp[0], q1 = bp[1], q2 = bp[2], q3 = bp[3];
            asm("fma.rn.f32x2 %0, %1, %2, %0;" : "+l"(acc[0]) : "l"(a2), "l"(q0.x));
            asm("fma.rn.f32x2 %0, %1, %2, %0;" : "+l"(acc[1]) : "l"(a2), "l"(q0.y));
            asm("fma.rn.f32x2 %0, %1, %2, %0;" : "+l"(acc[2]) : "l"(a2), "l"(q1.x));
            asm("fma.rn.f32x2 %0, %1, %2, %0;" : "+l"(acc[3]) : "l"(a2), "l"(q1.y));
            asm("fma.rn.f32x2 %0, %1, %2, %0;" : "+l"(acc[4]) : "l"(a2), "l"(q2.x));
            asm("fma.rn.f32x2 %0, %1, %2, %0;" : "+l"(acc[5]) : "l"(a2), "l"(q2.y));
            asm("fma.rn.f32x2 %0, %1, %2, %0;" : "+l"(acc[6]) : "l"(a2), "l"(q3.x));
            asm("fma.rn.f32x2 %0, %1, %2, %0;" : "+l"(acc[7]) : "l"(a2), "l"(q3.y));
        }
        __syncthreads();
    }

    // ---- LayerNorm + GELU ----
    float h[16];
#pragma unroll
    for (int i = 0; i < 8; i++)
        asm("mov.b64 {%0, %1}, %2;" : "=f"(h[2 * i]), "=f"(h[2 * i + 1]) : "l"(acc[i]));
    float s1 = 0.f;
#pragma unroll
    for (int i = 0; i < 16; i++) s1 += h[i];
    s1 += __shfl_xor_sync(0xffffffffu, s1, 1);
    s1 += __shfl_xor_sync(0xffffffffu, s1, 2);
    s1 += __shfl_xor_sync(0xffffffffu, s1, 4);
    float mu = s1 * (1.0f / 128.0f);
    float s2 = 0.f;
#pragma unroll
    for (int i = 0; i < 16; i++) { float d = h[i] - mu; s2 += d * d; }
    s2 += __shfl_xor_sync(0xffffffffu, s2, 1);
    s2 += __shfl_xor_sync(0xffffffffu, s2, 2);
    s2 += __shfl_xor_sync(0xffffffffu, s2, 4);
    float rstd = rsqrtf(s2 * (1.0f / 128.0f) + 1e-5f);
#pragma unroll
    for (int i = 0; i < 16; i++) {
        float v = (h[i] - mu) * rstd * lg[c0 + i] + lb[c0 + i];
        v = 0.5f * v * (1.0f + erff(v * 0.70710678118654752f));
        hs[r * 132 + c0 + i] = v;
    }
    __syncthreads();

    // ---- head weights into smem (overlay xs/ws) ----
    {
        const float4* sb = (const float4*)bnd_w1;
        const float4* sw = (const float4*)wkt_w1;
#pragma unroll
        for (int i = 0; i < 8; i++) {
            int f4 = t + 256 * i;
            int k = f4 >> 4, j0 = (f4 & 15) * 4;
            *(float4*)&hw[k * 128 + j0]      = sb[f4];
            *(float4*)&hw[k * 128 + 64 + j0] = sw[f4];
        }
    }
    __syncthreads();

    // ---- heads ----
    uint64_t ah[8];
    {
        const ulonglong2* bi = (const ulonglong2*)&b1s[c0];
        ulonglong2 p0 = bi[0], p1 = bi[1], p2 = bi[2], p3 = bi[3];
        ah[0] = p0.x; ah[1] = p0.y; ah[2] = p1.x; ah[3] = p1.y;
        ah[4] = p2.x; ah[5] = p2.y; ah[6] = p3.x; ah[7] = p3.y;
    }
#pragma unroll 4
    for (int k = 0; k < 128; k++) {
        float a = hs[r * 132 + k];
        uint64_t a2;
        asm("mov.b64 %0, {%1, %1};" : "=l"(a2) : "f"(a));
        const ulonglong2* bp = (const ulonglong2*)&hw[k * 128 + c0];
        ulonglong2 q0 = bp[0], q1 = bp[1], q2 = bp[2], q3 = bp[3];
        asm("fma.rn.f32x2 %0, %1, %2, %0;" : "+l"(ah[0]) : "l"(a2), "l"(q0.x));
        asm("fma.rn.f32x2 %0, %1, %2, %0;" : "+l"(ah[1]) : "l"(a2), "l"(q0.y));
        asm("fma.rn.f32x2 %0, %1, %2, %0;" : "+l"(ah[2]) : "l"(a2), "l"(q1.x));
        asm("fma.rn.f32x2 %0, %1, %2, %0;" : "+l"(ah[3]) : "l"(a2), "l"(q1.y));
        asm("fma.rn.f32x2 %0, %1, %2, %0;" : "+l"(ah[4]) : "l"(a2), "l"(q2.x));
        asm("fma.rn.f32x2 %0, %1, %2, %0;" : "+l"(ah[5]) : "l"(a2), "l"(q2.y));
        asm("fma.rn.f32x2 %0, %1, %2, %0;" : "+l"(ah[6]) : "l"(a2), "l"(q3.x));
        asm("fma.rn.f32x2 %0, %1, %2, %0;" : "+l"(ah[7]) : "l"(a2), "l"(q3.y));
    }
    float p = 0.f;
#pragma unroll
    for (int i = 0; i < 8; i++) {
        float lo, hi;
        asm("mov.b64 {%0, %1}, %2;" : "=f"(lo), "=f"(hi) : "l"(ah[i]));
        p += fmaxf(lo, 0.f) * w2s[c0 + 2 * i] + fmaxf(hi, 0.f) * w2s[c0 + 2 * i + 1];
    }
    p += __shfl_xor_sync(0xffffffffu, p, 1);
    p += __shfl_xor_sync(0xffffffffu, p, 2);
    int s = blk * 32 + r;
    if (cg == 0) out[s]      = p + bnd_b2[0];
    if (cg == 4) out[NB + s] = p + wkt_b2[0];
}

// ---------------------------------------------------------------------------
extern "C" void kernel_launch(void* const* d_in, const int* in_sizes, int n_in,
                              void* d_out, int out_size) {
    const float* query = (const float*)d_in[0];
    const float* ball  = (const float*)d_in[1];
    const int*   batch = (const int*)d_in[2];
    const float* aw1 = (const float*)d_in[3];
    const float* ab1 = (const float*)d_in[4];
    const float* aw2 = (const float*)d_in[5];
    const float* ab2 = (const float*)d_in[6];
    const float* cw  = (const float*)d_in[7];
    const float* cb  = (const float*)d_in[8];
    const float* lg  = (const float*)d_in[9];
    const float* lb  = (const float*)d_in[10];
    const float* bw1 = (const float*)d_in[11];
    const float* bb1 = (const float*)d_in[12];
    const float* bw2 = (const float*)d_in[13];
    const float* bb2 = (const float*)d_in[14];
    const float* ww1 = (const float*)d_in[15];
    const float* wb1 = (const float*)d_in[16];
    const float* ww2 = (const float*)d_in[17];
    const float* wb2 = (const float*)d_in[18];
    float* out = (float*)d_out;

    constexpr int mlp_smem = MS_TOT * (int)sizeof(float);
    cudaFuncSetAttribute(scores_mma,
                         cudaFuncAttributeMaxDynamicSharedMemorySize, SC_SMEM);
    cudaFuncSetAttribute(mlp_kernel,
                         cudaFuncAttributeMaxDynamicSharedMemorySize, mlp_smem);

    scores_mma<<<NBLK, 512, SC_SMEM>>>(ball, batch, aw1, ab1, aw2, ab2);
    mlp_kernel<<<NB / 32, 256, mlp_smem>>>(query, cw, cb, lg, lb,
                                           bw1, bb1, bw2, bb2,
                                           ww1, wb1, ww2, wb2, out);
}

// round 5
// speedup vs baseline: 1.9037x; 1.7540x over previous
#include <cuda_runtime.h>
#include <math.h>
#include <stdint.h>

#define NB    4096
#define NN    524288
#define HDIM  128
#define NBLK  (NN / 128)

// ---------------- static device scratch ----------------
__device__ int   g_off[NB + 1];
__device__ float g_frag_m [NB + NBLK];
__device__ float g_frag_se[NB + NBLK];
__device__ float g_frag_v [(size_t)(NB + NBLK) * 128];

// ---------------- helpers ----------------
__device__ __forceinline__ float fast_tanh(float x) {
    float e = __expf(2.0f * x);
    return 1.0f - __fdividef(2.0f, e + 1.0f);
}
// split (even,odd) f32 pair into bf16x2 hi + bf16x2 lo(residual); lo half = even
__device__ __forceinline__ void pack2(float e, float o, uint32_t& h, uint32_t& l) {
    asm("cvt.rn.bf16x2.f32 %0, %1, %2;" : "=r"(h) : "f"(o), "f"(e));
    float re = e - __uint_as_float(h << 16);
    float ro = o - __uint_as_float(h & 0xffff0000u);
    asm("cvt.rn.bf16x2.f32 %0, %1, %2;" : "=r"(l) : "f"(ro), "f"(re));
}
__device__ __forceinline__ void mma_bf16(float c[4], const uint32_t a[4],
                                         uint32_t b0, uint32_t b1) {
    asm volatile("mma.sync.aligned.m16n8k16.row.col.f32.bf16.bf16.f32 "
        "{%0,%1,%2,%3}, {%4,%5,%6,%7}, {%8,%9}, {%0,%1,%2,%3};"
        : "+f"(c[0]), "+f"(c[1]), "+f"(c[2]), "+f"(c[3])
        : "r"(a[0]), "r"(a[1]), "r"(a[2]), "r"(a[3]), "r"(b0), "r"(b1));
}
__device__ __forceinline__ uint64_t dup2(float x) {
    uint64_t r;
    asm("mov.b64 %0, {%1, %1};" : "=l"(r) : "f"(x));
    return r;
}
#define FMA2(acc, a, b) \
    asm("fma.rn.f32x2 %0, %1, %2, %0;" : "+l"(acc) : "l"(a), "l"(b))

// scores smem (u32 units): Ah[128][68], Al[128][68], Bh[64][68], Bl[64][68]
#define SLD 68
#define OFF_AL (128 * SLD)
#define OFF_BH (256 * SLD)
#define OFF_BL (256 * SLD + 64 * SLD)
#define SC_SMEM ((256 * SLD + 128 * SLD) * 4)   // 104448 B

// ===========================================================================
// Kernel 1: bf16 3-term mma.sync scores GEMM + fused fragment softmax
// 512 threads; warp w: m-strip (w>>1)*16, n-half (w&1)*32.
// ===========================================================================
__global__ __launch_bounds__(512, 2) void scores_mma(
    const float* __restrict__ ball, const int* __restrict__ batch,
    const float* __restrict__ w1, const float* __restrict__ b1,
    const float* __restrict__ w2, const float* __restrict__ b2)
{
    extern __shared__ uint32_t su[];
    uint32_t* Ah = su;
    uint32_t* Al = su + OFF_AL;
    uint32_t* Bh = su + OFF_BH;
    uint32_t* Bl = su + OFF_BL;

    __shared__ float sc[128], esc[128], fm[128];
    __shared__ float w2s[64], b1s[64];
    __shared__ float scpart[2][128];
    __shared__ float pv[4][128];
    __shared__ int   bbs[128], fid_s[128], fstart[128], fend[128], wcnt[4];

    const int t = threadIdx.x, blk = blockIdx.x;
    const int wid = t >> 5, lane = t & 31;

    // ---- load + split A tile (128x128 f32 -> bf16 hi/lo packed) ----
    {
        const float4* Ag = (const float4*)(ball + (size_t)blk * 128 * HDIM);
#pragma unroll
        for (int it = 0; it < 8; it++) {
            int f4 = t + 512 * it;
            int row = f4 >> 5, c4 = f4 & 31;
            float4 v = Ag[f4];
            uint32_t h0, l0, h1, l1;
            pack2(v.x, v.y, h0, l0);
            pack2(v.z, v.w, h1, l1);
            int base = row * SLD + c4 * 2;
            Ah[base] = h0; Ah[base + 1] = h1;
            Al[base] = l0; Al[base + 1] = l1;
        }
    }
    // ---- load + split W1^T: Bh/Bl[n][k2] ----
    {
#pragma unroll
        for (int i = 0; i < 8; i++) {
            int idx = t + 512 * i;             // 4096 = 64 n x 64 k2
            int n = idx & 63, k2 = idx >> 6;
            float xe = w1[(2 * k2) * 64 + n];
            float xo = w1[(2 * k2) * 64 + 64 + n];
            uint32_t h, l;
            pack2(xe, xo, h, l);
            Bh[n * SLD + k2] = h;
            Bl[n * SLD + k2] = l;
        }
    }
    if (t < 64) { w2s[t] = w2[t]; b1s[t] = b1[t]; }
    if (t >= 64 && t < 192) bbs[t - 64] = batch[blk * 128 + (t - 64)];
    __syncthreads();

    // ---- segment offsets (inline) ----
    if (t < 128) {
        int myb = bbs[t];
        int pb = (t == 0) ? ((blk == 0) ? -1 : batch[blk * 128 - 1]) : bbs[t - 1];
        for (int s2 = pb + 1; s2 <= myb; s2++) g_off[s2] = blk * 128 + t;
        if (blk == NBLK - 1 && t == 127)
            for (int s2 = myb + 1; s2 <= NB; s2++) g_off[s2] = NN;
    }

    // ---- GEMM: C[m16][n32] per warp, 3-term bf16 ----
    const int m0 = (wid >> 1) * 16;
    const int n0 = (wid & 1) * 32;
    const int lr = lane >> 2, lc = lane & 3;

    float c[4][4];
#pragma unroll
    for (int j = 0; j < 4; j++)
#pragma unroll
        for (int i = 0; i < 4; i++) c[j][i] = 0.f;

    const uint32_t* ArH  = &Ah[(m0 + lr) * SLD + lc];
    const uint32_t* ArH8 = ArH + 8 * SLD;
    const uint32_t* ArL  = &Al[(m0 + lr) * SLD + lc];
    const uint32_t* ArL8 = ArL + 8 * SLD;

#pragma unroll
    for (int kt = 0; kt < 8; kt++) {
        int kb = kt * 8;
        uint32_t ah[4] = {ArH[kb], ArH8[kb], ArH[kb + 4], ArH8[kb + 4]};
        uint32_t al[4] = {ArL[kb], ArL8[kb], ArL[kb + 4], ArL8[kb + 4]};
#pragma unroll
        for (int j = 0; j < 4; j++) {
            int n = n0 + j * 8 + lr;
            uint32_t bh0 = Bh[n * SLD + kb + lc];
            uint32_t bh1 = Bh[n * SLD + kb + lc + 4];
            uint32_t bl0 = Bl[n * SLD + kb + lc];
            uint32_t bl1 = Bl[n * SLD + kb + lc + 4];
            mma_bf16(c[j], ah, bh0, bh1);
            mma_bf16(c[j], al, bh0, bh1);
            mma_bf16(c[j], ah, bl0, bl1);
        }
    }

    // ---- epilogue: tanh(h + b1) . w2 -> per-row partials ----
    {
        float p0 = 0.f, p1 = 0.f;
#pragma unroll
        for (int j = 0; j < 4; j++) {
            int col0 = n0 + j * 8 + 2 * lc;
            float wa = w2s[col0], wb = w2s[col0 + 1];
            float ba = b1s[col0], bb = b1s[col0 + 1];
            p0 += fast_tanh(c[j][0] + ba) * wa + fast_tanh(c[j][1] + bb) * wb;
            p1 += fast_tanh(c[j][2] + ba) * wa + fast_tanh(c[j][3] + bb) * wb;
        }
        p0 += __shfl_xor_sync(0xffffffffu, p0, 1);
        p0 += __shfl_xor_sync(0xffffffffu, p0, 2);
        p1 += __shfl_xor_sync(0xffffffffu, p1, 1);
        p1 += __shfl_xor_sync(0xffffffffu, p1, 2);
        if (lc == 0) {
            scpart[wid & 1][m0 + lr]     = p0;
            scpart[wid & 1][m0 + lr + 8] = p1;
        }
    }
    __syncthreads();
    if (t < 128) sc[t] = scpart[0][t] + scpart[1][t] + b2[0];
    __syncthreads();

    // ---- fragment ids ----
    int newf = 0, last = 0, fid = 0;
    unsigned bal = 0;
    if (t < 128) {
        newf = (t == 0) ? 1 : (bbs[t] != bbs[t - 1]);
        bal = __ballot_sync(0xffffffffu, newf);
        if (lane == 0) wcnt[wid] = __popc(bal);
        last = (t == 127) ? 1 : (bbs[t + 1] != bbs[t]);
    }
    __syncthreads();
    if (t < 128) {
        int base = 0;
        for (int wq = 0; wq < wid; wq++) base += wcnt[wq];
        fid = base + __popc(bal & ((2u << lane) - 1u)) - 1;
        fid_s[t] = fid;
        if (newf) fstart[fid] = t;
        if (last) fend[fid] = t + 1;
    }
    __syncthreads();
    const int nf = fid_s[127] + 1;

    // ---- per-fragment max & sumexp ----
    if (t < nf) {
        int fs = fstart[t], fe = fend[t];
        float m = -3.4e38f;
        for (int i = fs; i < fe; i++) m = fmaxf(m, sc[i]);
        float se = 0.f;
        for (int i = fs; i < fe; i++) se += __expf(sc[i] - m);
        fm[t] = m;
        int id = bbs[fs] + blk;
        g_frag_m[id]  = m;
        g_frag_se[id] = se;
    }
    __syncthreads();
    if (t < 128) esc[t] = __expf(sc[t] - fm[fid_s[t]]);
    __syncthreads();

    // ---- fragment weighted feature sums (4 threads per column) ----
    {
        int col = t & 127, q = t >> 7;
        int k2 = col >> 1;
        int odd = col & 1;
        for (int f = 0; f < nf; f++) {
            int fs = fstart[f], fe = fend[f];
            float a = 0.f;
            for (int i = fs + q; i < fe; i += 4) {
                uint32_t h = Ah[i * SLD + k2], l = Al[i * SLD + k2];
                float av = odd
                    ? (__uint_as_float(h & 0xffff0000u) + __uint_as_float(l & 0xffff0000u))
                    : (__uint_as_float(h << 16) + __uint_as_float(l << 16));
                a += esc[i] * av;
            }
            pv[q][col] = a;
            __syncthreads();
            if (q == 0) {
                int id = bbs[fs] + blk;
                g_frag_v[(size_t)id * 128 + col] =
                    (pv[0][col] + pv[1][col]) + (pv[2][col] + pv[3][col]);
            }
            __syncthreads();
        }
    }
}

// ===========================================================================
// Kernel 2: fragment reduce + combiner GEMM + LN + GELU + heads.
// 128 blocks x 256 threads (8 warps), 32 rows per block; warp owns 4 rows.
// Conflict-free: x transposed [k][row] (broadcast reads), weights LDS.128.
// ===========================================================================
#define XTLD 36
#define M2_XST 0                      // xst: 256 x 36       = 9216
#define M2_WS  (256 * XTLD)           // ws:  64 x 128 chunk = 8192 -> 17408
#define M2_HST (M2_WS + 64 * 128)     // hst: 32 x 132       = 4224 -> 21632
#define M2_TOT (M2_HST + 32 * 132)    // 86528 B

__global__ __launch_bounds__(256) void mlp_kernel(
    const float* __restrict__ query,
    const float* __restrict__ comb_w, const float* __restrict__ comb_b,
    const float* __restrict__ ln_g, const float* __restrict__ ln_b,
    const float* __restrict__ bnd_w1, const float* __restrict__ bnd_b1,
    const float* __restrict__ bnd_w2, const float* __restrict__ bnd_b2,
    const float* __restrict__ wkt_w1, const float* __restrict__ wkt_b1,
    const float* __restrict__ wkt_w2, const float* __restrict__ wkt_b2,
    float* __restrict__ out)
{
    extern __shared__ float ms[];
    float* xst = ms + M2_XST;     // [k=256][row pad 36]
    float* ws  = ms + M2_WS;      // [k=64][c=128] chunk
    float* hw  = ms;              // overlays xst+ws: [k=128][c=128]
    float* hst = ms + M2_HST;     // [row=32][c pad 132]

    const int t = threadIdx.x, blk = blockIdx.x;
    const int wid = t >> 5, lane = t & 31;

    // ---- phase 0: fragment reduce -> xst (transposed [k][row]) ----
    {
        int r = t >> 3, cg = t & 7, c0 = cg * 16;
        int s = blk * 32 + r;
        float pooled[16];
#pragma unroll
        for (int j = 0; j < 16; j++) pooled[j] = 0.f;
        int o0 = g_off[s], o1 = g_off[s + 1];
        if (o0 < o1) {
            int kb0 = o0 >> 7, kb1 = (o1 - 1) >> 7;
            float M = -3.4e38f;
            for (int k = kb0; k <= kb1; k++) M = fmaxf(M, g_frag_m[s + k]);
            float denom = 0.f;
            for (int k = kb0; k <= kb1; k++)
                denom += g_frag_se[s + k] * __expf(g_frag_m[s + k] - M);
            float inv = 1.0f / denom;
            for (int k = kb0; k <= kb1; k++) {
                float wg = __expf(g_frag_m[s + k] - M) * inv;
                const float* v = g_frag_v + (size_t)(s + k) * 128 + c0;
#pragma unroll
                for (int j = 0; j < 16; j++) pooled[j] += v[j] * wg;
            }
        }
        const float* q = query + (size_t)s * 128 + c0;
#pragma unroll
        for (int j = 0; j < 16; j++) xst[(c0 + j) * XTLD + r] = q[j];
#pragma unroll
        for (int j = 0; j < 16; j++) xst[(128 + c0 + j) * XTLD + r] = pooled[j];
    }
    __syncthreads();

    const int r0 = wid * 4;                // this warp's 4 rows
    const int cl = lane * 4;               // this thread's 4 columns

    // ---- combiner GEMM: acc[p] = rows r0+p, cols cl..cl+3 ----
    uint64_t acc[4][2];
    {
        float4 cbv = *(const float4*)&comb_b[cl];
#pragma unroll
        for (int p = 0; p < 4; p++) {
            uint64_t i0, i1;
            asm("mov.b64 %0, {%1, %2};" : "=l"(i0) : "f"(cbv.x), "f"(cbv.y));
            asm("mov.b64 %0, {%1, %2};" : "=l"(i1) : "f"(cbv.z), "f"(cbv.w));
            acc[p][0] = i0; acc[p][1] = i1;
        }
    }
    for (int kt = 0; kt < 4; kt++) {
        const float4* src = (const float4*)(comb_w + kt * 64 * 128);
#pragma unroll
        for (int i = 0; i < 8; i++) {
            int f4 = t + 256 * i;
            ((float4*)ws)[f4] = src[f4];
        }
        __syncthreads();
#pragma unroll 4
        for (int kk = 0; kk < 64; kk++) {
            float4 xa = *(const float4*)&xst[(kt * 64 + kk) * XTLD + r0]; // broadcast
            ulonglong2 wq = *(const ulonglong2*)&ws[kk * 128 + cl];
            uint64_t d0 = dup2(xa.x), d1 = dup2(xa.y), d2 = dup2(xa.z), d3 = dup2(xa.w);
            FMA2(acc[0][0], d0, wq.x); FMA2(acc[0][1], d0, wq.y);
            FMA2(acc[1][0], d1, wq.x); FMA2(acc[1][1], d1, wq.y);
            FMA2(acc[2][0], d2, wq.x); FMA2(acc[2][1], d2, wq.y);
            FMA2(acc[3][0], d3, wq.x); FMA2(acc[3][1], d3, wq.y);
        }
        __syncthreads();
    }

    // ---- LayerNorm + GELU (per row, fully in-warp) + store hst ----
    {
        float4 lgv = *(const float4*)&ln_g[cl];
        float4 lbv = *(const float4*)&ln_b[cl];
#pragma unroll
        for (int p = 0; p < 4; p++) {
            float h[4];
            asm("mov.b64 {%0, %1}, %2;" : "=f"(h[0]), "=f"(h[1]) : "l"(acc[p][0]));
            asm("mov.b64 {%0, %1}, %2;" : "=f"(h[2]), "=f"(h[3]) : "l"(acc[p][1]));
            float s1 = (h[0] + h[1]) + (h[2] + h[3]);
#pragma unroll
            for (int o = 16; o; o >>= 1) s1 += __shfl_xor_sync(0xffffffffu, s1, o);
            float mu = s1 * (1.0f / 128.0f);
            float s2 = 0.f;
#pragma unroll
            for (int j = 0; j < 4; j++) { float d = h[j] - mu; s2 += d * d; }
#pragma unroll
            for (int o = 16; o; o >>= 1) s2 += __shfl_xor_sync(0xffffffffu, s2, o);
            float rstd = rsqrtf(s2 * (1.0f / 128.0f) + 1e-5f);
            float g4[4] = {lgv.x, lgv.y, lgv.z, lgv.w};
            float b4[4] = {lbv.x, lbv.y, lbv.z, lbv.w};
            float4 vo;
            float* vp = &vo.x;
#pragma unroll
            for (int j = 0; j < 4; j++) {
                float v = (h[j] - mu) * rstd * g4[j] + b4[j];
                vp[j] = 0.5f * v * (1.0f + erff(v * 0.70710678118654752f));
            }
            *(float4*)&hst[(r0 + p) * 132 + cl] = vo;
        }
    }

    // ---- load combined head weights [bnd | wkt] into hw (overlay) ----
    {
        const float4* sb = (const float4*)bnd_w1;
        const float4* sw = (const float4*)wkt_w1;
#pragma unroll
        for (int i = 0; i < 8; i++) {
            int f4 = t + 256 * i;
            int k = f4 >> 4, j0 = (f4 & 15) * 4;
            *(float4*)&hw[k * 128 + j0]      = sb[f4];
            *(float4*)&hw[k * 128 + 64 + j0] = sw[f4];
        }
    }
    __syncthreads();

    // ---- heads: thread = cols cl..cl+3 (lane<16 -> bnd, else wkt) ----
    uint64_t ha[4][2];
    float4 b1v = (lane < 16) ? *(const float4*)&bnd_b1[cl]
                             : *(const float4*)&wkt_b1[cl - 64];
    float4 w2v = (lane < 16) ? *(const float4*)&bnd_w2[cl]
                             : *(const float4*)&wkt_w2[cl - 64];
    {
#pragma unroll
        for (int p = 0; p < 4; p++) {
            uint64_t i0, i1;
            asm("mov.b64 %0, {%1, %2};" : "=l"(i0) : "f"(b1v.x), "f"(b1v.y));
            asm("mov.b64 %0, {%1, %2};" : "=l"(i1) : "f"(b1v.z), "f"(b1v.w));
            ha[p][0] = i0; ha[p][1] = i1;
        }
    }
#pragma unroll 4
    for (int k = 0; k < 128; k++) {
        ulonglong2 wq = *(const ulonglong2*)&hw[k * 128 + cl];
        float x0 = hst[(r0 + 0) * 132 + k];
        float x1 = hst[(r0 + 1) * 132 + k];
        float x2 = hst[(r0 + 2) * 132 + k];
        float x3 = hst[(r0 + 3) * 132 + k];
        uint64_t d0 = dup2(x0), d1 = dup2(x1), d2 = dup2(x2), d3 = dup2(x3);
        FMA2(ha[0][0], d0, wq.x); FMA2(ha[0][1], d0, wq.y);
        FMA2(ha[1][0], d1, wq.x); FMA2(ha[1][1], d1, wq.y);
        FMA2(ha[2][0], d2, wq.x); FMA2(ha[2][1], d2, wq.y);
        FMA2(ha[3][0], d3, wq.x); FMA2(ha[3][1], d3, wq.y);
    }
    {
        float w4[4] = {w2v.x, w2v.y, w2v.z, w2v.w};
#pragma unroll
        for (int p = 0; p < 4; p++) {
            float v[4];
            asm("mov.b64 {%0, %1}, %2;" : "=f"(v[0]), "=f"(v[1]) : "l"(ha[p][0]));
            asm("mov.b64 {%0, %1}, %2;" : "=f"(v[2]), "=f"(v[3]) : "l"(ha[p][1]));
            float part = 0.f;
#pragma unroll
            for (int j = 0; j < 4; j++) part += fmaxf(v[j], 0.f) * w4[j];
            // reduce within 16-lane halves (bnd: lanes 0-15, wkt: 16-31)
            part += __shfl_xor_sync(0xffffffffu, part, 1);
            part += __shfl_xor_sync(0xffffffffu, part, 2);
            part += __shfl_xor_sync(0xffffffffu, part, 4);
            part += __shfl_xor_sync(0xffffffffu, part, 8);
            int s = blk * 32 + r0 + p;
            if (lane == 0)  out[s]      = part + bnd_b2[0];
            if (lane == 16) out[NB + s] = part + wkt_b2[0];
        }
    }
}

// ---------------------------------------------------------------------------
extern "C" void kernel_launch(void* const* d_in, const int* in_sizes, int n_in,
                              void* d_out, int out_size) {
    const float* query = (const float*)d_in[0];
    const float* ball  = (const float*)d_in[1];
    const int*   batch = (const int*)d_in[2];
    const float* aw1 = (const float*)d_in[3];
    const float* ab1 = (const float*)d_in[4];
    const float* aw2 = (const float*)d_in[5];
    const float* ab2 = (const float*)d_in[6];
    const float* cw  = (const float*)d_in[7];
    const float* cb  = (const float*)d_in[8];
    const float* lg  = (const float*)d_in[9];
    const float* lb  = (const float*)d_in[10];
    const float* bw1 = (const float*)d_in[11];
    const float* bb1 = (const float*)d_in[12];
    const float* bw2 = (const float*)d_in[13];
    const float* bb2 = (const float*)d_in[14];
    const float* ww1 = (const float*)d_in[15];
    const float* wb1 = (const float*)d_in[16];
    const float* ww2 = (const float*)d_in[17];
    const float* wb2 = (const float*)d_in[18];
    float* out = (float*)d_out;

    constexpr int mlp_smem = M2_TOT * (int)sizeof(float);
    cudaFuncSetAttribute(scores_mma,
                         cudaFuncAttributeMaxDynamicSharedMemorySize, SC_SMEM);
    cudaFuncSetAttribute(mlp_kernel,
                         cudaFuncAttributeMaxDynamicSharedMemorySize, mlp_smem);

    scores_mma<<<NBLK, 512, SC_SMEM>>>(ball, batch, aw1, ab1, aw2, ab2);
    mlp_kernel<<<NB / 32, 256, mlp_smem>>>(query, cw, cb, lg, lb,
                                           bw1, bb1, bw2, bb2,
                                           ww1, wb1, ww2, wb2, out);
}

// round 6
// speedup vs baseline: 2.1842x; 1.1474x over previous
#include <cuda_runtime.h>
#include <cuda_fp16.h>
#include <math.h>
#include <stdint.h>

#define NB    4096
#define NN    524288
#define HDIM  128
#define NBLK  (NN / 128)

// ---------------- static device scratch ----------------
__device__ int   g_off[NB + 1];
__device__ float g_frag_m [NB + NBLK];
__device__ float g_frag_se[NB + NBLK];
__device__ float g_frag_v [(size_t)(NB + NBLK) * 128];

// ---------------- helpers ----------------
__device__ __forceinline__ float fast_tanh(float x) {
    float e = __expf(2.0f * x);
    return 1.0f - __fdividef(2.0f, e + 1.0f);
}
// split (even,odd) f32 pair into f16x2 hi + f16x2 lo(residual); low half = even
__device__ __forceinline__ void pack2h(float e, float o, uint32_t& h, uint32_t& l) {
    __half2 hh = __floats2half2_rn(e, o);
    float fe = __low2float(hh), fo = __high2float(hh);
    __half2 ll = __floats2half2_rn(e - fe, o - fo);
    h = *(uint32_t*)&hh;
    l = *(uint32_t*)&ll;
}
__device__ __forceinline__ void mma_f16(float c[4], const uint32_t a[4],
                                        uint32_t b0, uint32_t b1) {
    asm volatile("mma.sync.aligned.m16n8k16.row.col.f32.f16.f16.f32 "
        "{%0,%1,%2,%3}, {%4,%5,%6,%7}, {%8,%9}, {%0,%1,%2,%3};"
        : "+f"(c[0]), "+f"(c[1]), "+f"(c[2]), "+f"(c[3])
        : "r"(a[0]), "r"(a[1]), "r"(a[2]), "r"(a[3]), "r"(b0), "r"(b1));
}
__device__ __forceinline__ uint64_t dup2(float x) {
    uint64_t r;
    asm("mov.b64 %0, {%1, %1};" : "=l"(r) : "f"(x));
    return r;
}
#define FMA2(acc, a, b) \
    asm("fma.rn.f32x2 %0, %1, %2, %0;" : "+l"(acc) : "l"(a), "l"(b))

// scores smem (u32 units): Ah[128][68], Al[128][68], Bh[64][68]
#define SLD 68
#define OFF_AL (128 * SLD)
#define OFF_BH (256 * SLD)
#define SC_SMEM ((256 * SLD + 64 * SLD) * 4)   // 87040 B

// ===========================================================================
// Kernel 1: fp16 2-term mma.sync scores GEMM + fused fragment softmax
// 512 threads; warp w: m-strip (w>>1)*16, n-half (w&1)*32.
// ===========================================================================
__global__ __launch_bounds__(512, 2) void scores_mma(
    const float* __restrict__ ball, const int* __restrict__ batch,
    const float* __restrict__ w1, const float* __restrict__ b1,
    const float* __restrict__ w2, const float* __restrict__ b2)
{
    extern __shared__ uint32_t su[];
    uint32_t* Ah = su;
    uint32_t* Al = su + OFF_AL;
    uint32_t* Bh = su + OFF_BH;

    __shared__ float sc[128], esc[128], fm[128];
    __shared__ float w2s[64], b1s[64];
    __shared__ float scpart[2][128];
    __shared__ float pv[4][128];
    __shared__ int   bbs[128], fid_s[128], fstart[128], fend[128], wcnt[4];

    const int t = threadIdx.x, blk = blockIdx.x;
    const int wid = t >> 5, lane = t & 31;

    // ---- load + split A tile (128x128 f32 -> f16 hi/lo packed) ----
    {
        const float4* Ag = (const float4*)(ball + (size_t)blk * 128 * HDIM);
#pragma unroll
        for (int it = 0; it < 8; it++) {
            int f4 = t + 512 * it;
            int row = f4 >> 5, c4 = f4 & 31;
            float4 v = Ag[f4];
            uint32_t h0, l0, h1, l1;
            pack2h(v.x, v.y, h0, l0);
            pack2h(v.z, v.w, h1, l1);
            int base = row * SLD + c4 * 2;
            Ah[base] = h0; Ah[base + 1] = h1;
            Al[base] = l0; Al[base + 1] = l1;
        }
    }
    // ---- load W1^T single fp16: Bh[n][k2] ----
    {
#pragma unroll
        for (int i = 0; i < 8; i++) {
            int idx = t + 512 * i;             // 4096 = 64 n x 64 k2
            int n = idx & 63, k2 = idx >> 6;
            float xe = w1[(2 * k2) * 64 + n];
            float xo = w1[(2 * k2) * 64 + 64 + n];
            __half2 hh = __floats2half2_rn(xe, xo);
            Bh[n * SLD + k2] = *(uint32_t*)&hh;
        }
    }
    if (t < 64) { w2s[t] = w2[t]; b1s[t] = b1[t]; }
    if (t >= 64 && t < 192) bbs[t - 64] = batch[blk * 128 + (t - 64)];
    __syncthreads();

    // ---- segment offsets (inline) ----
    if (t < 128) {
        int myb = bbs[t];
        int pb = (t == 0) ? ((blk == 0) ? -1 : batch[blk * 128 - 1]) : bbs[t - 1];
        for (int s2 = pb + 1; s2 <= myb; s2++) g_off[s2] = blk * 128 + t;
        if (blk == NBLK - 1 && t == 127)
            for (int s2 = myb + 1; s2 <= NB; s2++) g_off[s2] = NN;
    }

    // ---- GEMM: C[m16][n32] per warp, 2-term fp16 ----
    const int m0 = (wid >> 1) * 16;
    const int n0 = (wid & 1) * 32;
    const int lr = lane >> 2, lc = lane & 3;

    float c[4][4];
#pragma unroll
    for (int j = 0; j < 4; j++)
#pragma unroll
        for (int i = 0; i < 4; i++) c[j][i] = 0.f;

    const uint32_t* ArH  = &Ah[(m0 + lr) * SLD + lc];
    const uint32_t* ArH8 = ArH + 8 * SLD;
    const uint32_t* ArL  = &Al[(m0 + lr) * SLD + lc];
    const uint32_t* ArL8 = ArL + 8 * SLD;

#pragma unroll
    for (int kt = 0; kt < 8; kt++) {
        int kb = kt * 8;
        uint32_t ah[4] = {ArH[kb], ArH8[kb], ArH[kb + 4], ArH8[kb + 4]};
        uint32_t al[4] = {ArL[kb], ArL8[kb], ArL[kb + 4], ArL8[kb + 4]};
#pragma unroll
        for (int j = 0; j < 4; j++) {
            int n = n0 + j * 8 + lr;
            uint32_t bh0 = Bh[n * SLD + kb + lc];
            uint32_t bh1 = Bh[n * SLD + kb + lc + 4];
            mma_f16(c[j], ah, bh0, bh1);
            mma_f16(c[j], al, bh0, bh1);
        }
    }

    // ---- epilogue: tanh(h + b1) . w2 -> per-row partials ----
    {
        float p0 = 0.f, p1 = 0.f;
#pragma unroll
        for (int j = 0; j < 4; j++) {
            int col0 = n0 + j * 8 + 2 * lc;
            float wa = w2s[col0], wb = w2s[col0 + 1];
            float ba = b1s[col0], bb = b1s[col0 + 1];
            p0 += fast_tanh(c[j][0] + ba) * wa + fast_tanh(c[j][1] + bb) * wb;
            p1 += fast_tanh(c[j][2] + ba) * wa + fast_tanh(c[j][3] + bb) * wb;
        }
        p0 += __shfl_xor_sync(0xffffffffu, p0, 1);
        p0 += __shfl_xor_sync(0xffffffffu, p0, 2);
        p1 += __shfl_xor_sync(0xffffffffu, p1, 1);
        p1 += __shfl_xor_sync(0xffffffffu, p1, 2);
        if (lc == 0) {
            scpart[wid & 1][m0 + lr]     = p0;
            scpart[wid & 1][m0 + lr + 8] = p1;
        }
    }
    __syncthreads();
    if (t < 128) sc[t] = scpart[0][t] + scpart[1][t] + b2[0];
    __syncthreads();

    // ---- fragment ids ----
    int newf = 0, last = 0, fid = 0;
    unsigned bal = 0;
    if (t < 128) {
        newf = (t == 0) ? 1 : (bbs[t] != bbs[t - 1]);
        bal = __ballot_sync(0xffffffffu, newf);
        if (lane == 0) wcnt[wid] = __popc(bal);
        last = (t == 127) ? 1 : (bbs[t + 1] != bbs[t]);
    }
    __syncthreads();
    if (t < 128) {
        int base = 0;
        for (int wq = 0; wq < wid; wq++) base += wcnt[wq];
        fid = base + __popc(bal & ((2u << lane) - 1u)) - 1;
        fid_s[t] = fid;
        if (newf) fstart[fid] = t;
        if (last) fend[fid] = t + 1;
    }
    __syncthreads();
    const int nf = fid_s[127] + 1;

    // ---- per-fragment max & sumexp ----
    if (t < nf) {
        int fs = fstart[t], fe = fend[t];
        float m = -3.4e38f;
        for (int i = fs; i < fe; i++) m = fmaxf(m, sc[i]);
        float se = 0.f;
        for (int i = fs; i < fe; i++) se += __expf(sc[i] - m);
        fm[t] = m;
        int id = bbs[fs] + blk;
        g_frag_m[id]  = m;
        g_frag_se[id] = se;
    }
    __syncthreads();
    if (t < 128) esc[t] = __expf(sc[t] - fm[fid_s[t]]);
    __syncthreads();

    // ---- fragment weighted feature sums (4 threads per column) ----
    {
        int col = t & 127, q = t >> 7;
        int k2 = col >> 1;
        int odd = col & 1;
        for (int f = 0; f < nf; f++) {
            int fs = fstart[f], fe = fend[f];
            float a = 0.f;
            for (int i = fs + q; i < fe; i += 4) {
                uint32_t h = Ah[i * SLD + k2], l = Al[i * SLD + k2];
                __half2 h2 = *(__half2*)&h;
                __half2 l2 = *(__half2*)&l;
                float av = odd ? (__high2float(h2) + __high2float(l2))
                               : (__low2float(h2) + __low2float(l2));
                a += esc[i] * av;
            }
            pv[q][col] = a;
            __syncthreads();
            if (q == 0) {
                int id = bbs[fs] + blk;
                g_frag_v[(size_t)id * 128 + col] =
                    (pv[0][col] + pv[1][col]) + (pv[2][col] + pv[3][col]);
            }
            __syncthreads();
        }
    }
}

// ===========================================================================
// Kernel 2: fragment reduce + combiner GEMM + LN + GELU + heads.
// 128 blocks x 512 threads (16 warps), 32 rows per block; warp owns 2 rows.
// ===========================================================================
#define XTLD 36
#define M2_XST 0                      // xst: 256 x 36
#define M2_WS  (256 * XTLD)           // ws:  64 x 128 chunk
#define M2_HST (M2_WS + 64 * 128)     // hst: 32 x 132
#define M2_TOT (M2_HST + 32 * 132)    // 86528 B

__global__ __launch_bounds__(512) void mlp_kernel(
    const float* __restrict__ query,
    const float* __restrict__ comb_w, const float* __restrict__ comb_b,
    const float* __restrict__ ln_g, const float* __restrict__ ln_b,
    const float* __restrict__ bnd_w1, const float* __restrict__ bnd_b1,
    const float* __restrict__ bnd_w2, const float* __restrict__ bnd_b2,
    const float* __restrict__ wkt_w1, const float* __restrict__ wkt_b1,
    const float* __restrict__ wkt_w2, const float* __restrict__ wkt_b2,
    float* __restrict__ out)
{
    extern __shared__ float ms[];
    float* xst = ms + M2_XST;     // [k=256][row pad 36]
    float* ws  = ms + M2_WS;      // [k=64][c=128] chunk
    float* hw  = ms;              // overlays xst+ws: [k=128][c=128]
    float* hst = ms + M2_HST;     // [row=32][c pad 132]

    const int t = threadIdx.x, blk = blockIdx.x;
    const int wid = t >> 5, lane = t & 31;

    // ---- phase 0: fragment reduce -> xst (transposed [k][row]) ----
    {
        int r = t >> 4, cg = t & 15, c0 = cg * 8;
        int s = blk * 32 + r;
        float pooled[8];
#pragma unroll
        for (int j = 0; j < 8; j++) pooled[j] = 0.f;
        int o0 = g_off[s], o1 = g_off[s + 1];
        if (o0 < o1) {
            int kb0 = o0 >> 7, kb1 = (o1 - 1) >> 7;
            float M = -3.4e38f;
            for (int k = kb0; k <= kb1; k++) M = fmaxf(M, g_frag_m[s + k]);
            float denom = 0.f;
            for (int k = kb0; k <= kb1; k++)
                denom += g_frag_se[s + k] * __expf(g_frag_m[s + k] - M);
            float inv = 1.0f / denom;
            for (int k = kb0; k <= kb1; k++) {
                float wg = __expf(g_frag_m[s + k] - M) * inv;
                const float* v = g_frag_v + (size_t)(s + k) * 128 + c0;
#pragma unroll
                for (int j = 0; j < 8; j++) pooled[j] += v[j] * wg;
            }
        }
        const float* q = query + (size_t)s * 128 + c0;
#pragma unroll
        for (int j = 0; j < 8; j++) xst[(c0 + j) * XTLD + r] = q[j];
#pragma unroll
        for (int j = 0; j < 8; j++) xst[(128 + c0 + j) * XTLD + r] = pooled[j];
    }
    __syncthreads();

    const int r0 = wid * 2;                // this warp's 2 rows
    const int cl = lane * 4;               // this thread's 4 columns

    // ---- combiner GEMM: acc[p] = rows r0+p, cols cl..cl+3 ----
    uint64_t acc[2][2];
    {
        float4 cbv = *(const float4*)&comb_b[cl];
#pragma unroll
        for (int p = 0; p < 2; p++) {
            uint64_t i0, i1;
            asm("mov.b64 %0, {%1, %2};" : "=l"(i0) : "f"(cbv.x), "f"(cbv.y));
            asm("mov.b64 %0, {%1, %2};" : "=l"(i1) : "f"(cbv.z), "f"(cbv.w));
            acc[p][0] = i0; acc[p][1] = i1;
        }
    }
    for (int kt = 0; kt < 4; kt++) {
        const float4* src = (const float4*)(comb_w + kt * 64 * 128);
#pragma unroll
        for (int i = 0; i < 4; i++) {
            int f4 = t + 512 * i;
            ((float4*)ws)[f4] = src[f4];
        }
        __syncthreads();
#pragma unroll 4
        for (int kk = 0; kk < 64; kk++) {
            float2 xa = *(const float2*)&xst[(kt * 64 + kk) * XTLD + r0]; // broadcast
            ulonglong2 wq = *(const ulonglong2*)&ws[kk * 128 + cl];
            uint64_t d0 = dup2(xa.x), d1 = dup2(xa.y);
            FMA2(acc[0][0], d0, wq.x); FMA2(acc[0][1], d0, wq.y);
            FMA2(acc[1][0], d1, wq.x); FMA2(acc[1][1], d1, wq.y);
        }
        __syncthreads();
    }

    // ---- LayerNorm + GELU (per row, fully in-warp) + store hst ----
    {
        float4 lgv = *(const float4*)&ln_g[cl];
        float4 lbv = *(const float4*)&ln_b[cl];
#pragma unroll
        for (int p = 0; p < 2; p++) {
            float h[4];
            asm("mov.b64 {%0, %1}, %2;" : "=f"(h[0]), "=f"(h[1]) : "l"(acc[p][0]));
            asm("mov.b64 {%0, %1}, %2;" : "=f"(h[2]), "=f"(h[3]) : "l"(acc[p][1]));
            float s1 = (h[0] + h[1]) + (h[2] + h[3]);
#pragma unroll
            for (int o = 16; o; o >>= 1) s1 += __shfl_xor_sync(0xffffffffu, s1, o);
            float mu = s1 * (1.0f / 128.0f);
            float s2 = 0.f;
#pragma unroll
            for (int j = 0; j < 4; j++) { float d = h[j] - mu; s2 += d * d; }
#pragma unroll
            for (int o = 16; o; o >>= 1) s2 += __shfl_xor_sync(0xffffffffu, s2, o);
            float rstd = rsqrtf(s2 * (1.0f / 128.0f) + 1e-5f);
            float g4[4] = {lgv.x, lgv.y, lgv.z, lgv.w};
            float b4[4] = {lbv.x, lbv.y, lbv.z, lbv.w};
            float4 vo;
            float* vp = &vo.x;
#pragma unroll
            for (int j = 0; j < 4; j++) {
                float v = (h[j] - mu) * rstd * g4[j] + b4[j];
                vp[j] = 0.5f * v * (1.0f + erff(v * 0.70710678118654752f));
            }
            *(float4*)&hst[(r0 + p) * 132 + cl] = vo;
        }
    }

    // ---- load combined head weights [bnd | wkt] into hw (overlay) ----
    {
        const float4* sb = (const float4*)bnd_w1;
        const float4* sw = (const float4*)wkt_w1;
#pragma unroll
        for (int i = 0; i < 4; i++) {
            int f4 = t + 512 * i;
            int k = f4 >> 4, j0 = (f4 & 15) * 4;
            *(float4*)&hw[k * 128 + j0]      = sb[f4];
            *(float4*)&hw[k * 128 + 64 + j0] = sw[f4];
        }
    }
    __syncthreads();

    // ---- heads: thread = cols cl..cl+3 (lane<16 -> bnd, else wkt) ----
    uint64_t ha[2][2];
    float4 b1v = (lane < 16) ? *(const float4*)&bnd_b1[cl]
                             : *(const float4*)&wkt_b1[cl - 64];
    float4 w2v = (lane < 16) ? *(const float4*)&bnd_w2[cl]
                             : *(const float4*)&wkt_w2[cl - 64];
    {
#pragma unroll
        for (int p = 0; p < 2; p++) {
            uint64_t i0, i1;
            asm("mov.b64 %0, {%1, %2};" : "=l"(i0) : "f"(b1v.x), "f"(b1v.y));
            asm("mov.b64 %0, {%1, %2};" : "=l"(i1) : "f"(b1v.z), "f"(b1v.w));
            ha[p][0] = i0; ha[p][1] = i1;
        }
    }
#pragma unroll 4
    for (int k = 0; k < 128; k++) {
        ulonglong2 wq = *(const ulonglong2*)&hw[k * 128 + cl];
        float x0 = hst[(r0 + 0) * 132 + k];
        float x1 = hst[(r0 + 1) * 132 + k];
        uint64_t d0 = dup2(x0), d1 = dup2(x1);
        FMA2(ha[0][0], d0, wq.x); FMA2(ha[0][1], d0, wq.y);
        FMA2(ha[1][0], d1, wq.x); FMA2(ha[1][1], d1, wq.y);
    }
    {
        float w4[4] = {w2v.x, w2v.y, w2v.z, w2v.w};
#pragma unroll
        for (int p = 0; p < 2; p++) {
            float v[4];
            asm("mov.b64 {%0, %1}, %2;" : "=f"(v[0]), "=f"(v[1]) : "l"(ha[p][0]));
            asm("mov.b64 {%0, %1}, %2;" : "=f"(v[2]), "=f"(v[3]) : "l"(ha[p][1]));
            float part = 0.f;
#pragma unroll
            for (int j = 0; j < 4; j++) part += fmaxf(v[j], 0.f) * w4[j];
            part += __shfl_xor_sync(0xffffffffu, part, 1);
            part += __shfl_xor_sync(0xffffffffu, part, 2);
            part += __shfl_xor_sync(0xffffffffu, part, 4);
            part += __shfl_xor_sync(0xffffffffu, part, 8);
            int s = blk * 32 + r0 + p;
            if (lane == 0)  out[s]      = part + bnd_b2[0];
            if (lane == 16) out[NB + s] = part + wkt_b2[0];
        }
    }
}

// ---------------------------------------------------------------------------
extern "C" void kernel_launch(void* const* d_in, const int* in_sizes, int n_in,
                              void* d_out, int out_size) {
    const float* query = (const float*)d_in[0];
    const float* ball  = (const float*)d_in[1];
    const int*   batch = (const int*)d_in[2];
    const float* aw1 = (const float*)d_in[3];
    const float* ab1 = (const float*)d_in[4];
    const float* aw2 = (const float*)d_in[5];
    const float* ab2 = (const float*)d_in[6];
    const float* cw  = (const float*)d_in[7];
    const float* cb  = (const float*)d_in[8];
    const float* lg  = (const float*)d_in[9];
    const float* lb  = (const float*)d_in[10];
    const float* bw1 = (const float*)d_in[11];
    const float* bb1 = (const float*)d_in[12];
    const float* bw2 = (const float*)d_in[13];
    const float* bb2 = (const float*)d_in[14];
    const float* ww1 = (const float*)d_in[15];
    const float* wb1 = (const float*)d_in[16];
    const float* ww2 = (const float*)d_in[17];
    const float* wb2 = (const float*)d_in[18];
    float* out = (float*)d_out;

    constexpr int mlp_smem = M2_TOT * (int)sizeof(float);
    cudaFuncSetAttribute(scores_mma,
                         cudaFuncAttributeMaxDynamicSharedMemorySize, SC_SMEM);
    cudaFuncSetAttribute(mlp_kernel,
                         cudaFuncAttributeMaxDynamicSharedMemorySize, mlp_smem);

    scores_mma<<<NBLK, 512, SC_SMEM>>>(ball, batch, aw1, ab1, aw2, ab2);
    mlp_kernel<<<NB / 32, 512, mlp_smem>>>(query, cw, cb, lg, lb,
                                           bw1, bb1, bw2, bb2,
                                           ww1, wb1, ww2, wb2, out);
}